// round 4
// baseline (speedup 1.0000x reference)
#include <cuda_runtime.h>
#include <cuda_bf16.h>

// Problem constants (fixed by the reference: B=16,S=16 -> BS=256)
#define L_TOK   128          // tokens per sentence
#define NARG    8            // A
#define NTOK    8            // T
#define EMB_D   768          // D
#define DC      128          // D-chunk per CTA
#define NCHUNK  (EMB_D / DC) // 6
#define NP      24           // 3 arg-sets * NARG
#define BDIM    128

// flat entry: l (bits 0..6) | w (bits 7..10) | p (bits 11..15)
struct SmemLayout {
    int            s_ids[L_TOK];
    float          s_m[L_TOK];
    int            s_arg[NP * NTOK];
    unsigned char  wtab[NP * L_TOK];     // 3 KB  per (p,l) match weight
    int            cnt[NP];              // entries per p
    int            cursor[NP];           // placement cursors
    int            offs[NP + 1];         // exclusive scan of cnt
    unsigned short flat[NP * L_TOK];     // 6 KB  events sorted by p
    int            s_tot[NP];            // total matched tokens per p
    float          s_inv[NP];            // 1/tot or 0
    float          s_minv;               // 1/max(sum(mask),1)
};

__global__ void __launch_bounds__(BDIM)
slmuse_fused_kernel(const int*   __restrict__ sent_ids,
                    const int*   __restrict__ att_mask,
                    const int*   __restrict__ pred_ids,
                    const int*   __restrict__ arg0_ids,
                    const int*   __restrict__ arg1_ids,
                    const float* __restrict__ emb,
                    float*       __restrict__ out,
                    int BS)
{
    __shared__ SmemLayout sm;

    const int tid   = threadIdx.x;
    const int bs    = blockIdx.x / NCHUNK;
    const int chunk = blockIdx.x % NCHUNK;

    float* out_mean = out;                               // [BS, D]
    float* out_sets = out + (size_t)BS * EMB_D;          // 3 x [BS, A, D]
    const size_t set_stride = (size_t)BS * NARG * EMB_D;

    // ---- Phase 1: stage ids / mask / arg ids ----
    if (tid < L_TOK) {
        sm.s_ids[tid] = sent_ids[(size_t)bs * L_TOK + tid];
        sm.s_m[tid]   = (float)att_mask[(size_t)bs * L_TOK + tid];
    }
    for (int i = tid; i < NP * NTOK; i += BDIM) {
        int p = i / NTOK, t = i % NTOK;
        int set = p / NARG, a = p % NARG;
        const int* src = (set == 0) ? pred_ids : (set == 1) ? arg0_ids : arg1_ids;
        sm.s_arg[i] = src[((size_t)bs * NARG + a) * NTOK + t];
    }
    if (tid < NP) { sm.cnt[tid] = 0; sm.s_tot[tid] = 0; }
    __syncthreads();

    // ---- Phase 2a: compute match weights, count per p ----
    for (int task = tid; task < NP * L_TOK; task += BDIM) {
        int p = task >> 7;
        int l = task & (L_TOK - 1);
        int sid = sm.s_ids[l];
        int w = 0;
        #pragma unroll
        for (int t = 0; t < NTOK; t++) {
            int aid = sm.s_arg[p * NTOK + t];
            w += (aid != 0 && aid == sid) ? 1 : 0;
        }
        sm.wtab[task] = (unsigned char)w;
        if (w) {
            atomicAdd(&sm.cnt[p], 1);
            atomicAdd(&sm.s_tot[p], w);
        }
    }
    __syncthreads();

    // ---- Phase 2b: scan offsets (single thread: 24 elems) ----
    if (tid == 0) {
        int run = 0;
        #pragma unroll
        for (int p = 0; p < NP; p++) { sm.offs[p] = run; run += sm.cnt[p]; }
        sm.offs[NP] = run;

        float ms = 0.f;
        #pragma unroll 8
        for (int l = 0; l < L_TOK; l++) ms += sm.s_m[l];
        sm.s_minv = 1.f / fmaxf(ms, 1.f);
    }
    __syncthreads();
    if (tid < NP) {
        sm.cursor[tid] = sm.offs[tid];
        int tot = sm.s_tot[tid];
        sm.s_inv[tid] = (tot > 0) ? (1.f / (float)tot) : 0.f;
    }
    __syncthreads();

    // ---- Phase 2c: place events into flat list sorted by p ----
    for (int task = tid; task < NP * L_TOK; task += BDIM) {
        int w = sm.wtab[task];
        if (w) {
            int p = task >> 7;
            int l = task & (L_TOK - 1);
            int pos = atomicAdd(&sm.cursor[p], 1);
            sm.flat[pos] = (unsigned short)(l | (w << 7) | (p << 11));
        }
    }
    __syncthreads();

    const float* col_base = emb + (size_t)bs * L_TOK * EMB_D
                                + (size_t)chunk * DC + tid;
    const size_t ocol = (size_t)chunk * DC + tid;

    // ---- Phase S: sparse arg sums, register-only p-sorted walk, MLP=8 ----
    {
        const int total = sm.offs[NP];
        float acc = 0.f;
        int curp = 0;

        for (int j0 = 0; j0 < total; j0 += 8) {
            float vals[8];
            int   es[8];
            #pragma unroll
            for (int k = 0; k < 8; k++) {
                int j = j0 + k;
                int e = (j < total) ? (int)sm.flat[j] : (NP << 11);  // sentinel
                es[k]   = e;
                vals[k] = (j < total) ? col_base[(size_t)(e & 127) * EMB_D] : 0.f;
            }
            #pragma unroll
            for (int k = 0; k < 8; k++) {
                int p = es[k] >> 11;
                if (p != curp) {                       // block-uniform branch
                    // emit curp (acc) and zeros for skipped p's
                    for (int q = curp; q < p && q < NP; q++) {
                        float res = (q == curp) ? acc * sm.s_inv[q] : 0.f;
                        int set = q >> 3, a = q & 7;
                        out_sets[(size_t)set * set_stride
                                 + ((size_t)bs * NARG + a) * EMB_D + ocol] = res;
                    }
                    curp = p;
                    acc  = 0.f;
                }
                acc += (float)((es[k] >> 7) & 15) * vals[k];
            }
        }
        // tail: remaining p's
        for (int q = curp; q < NP; q++) {
            float res = (q == curp) ? acc * sm.s_inv[q] : 0.f;
            int set = q >> 3, a = q & 7;
            out_sets[(size_t)set * set_stride
                     + ((size_t)bs * NARG + a) * EMB_D + ocol] = res;
        }
    }

    // ---- Phase M: mean pool, dense stream, MLP=8 ----
    {
        float a0 = 0.f, a1 = 0.f, a2 = 0.f, a3 = 0.f;
        float a4 = 0.f, a5 = 0.f, a6 = 0.f, a7 = 0.f;
        #pragma unroll 2
        for (int l = 0; l < L_TOK; l += 8) {
            float v0 = col_base[(size_t)(l + 0) * EMB_D];
            float v1 = col_base[(size_t)(l + 1) * EMB_D];
            float v2 = col_base[(size_t)(l + 2) * EMB_D];
            float v3 = col_base[(size_t)(l + 3) * EMB_D];
            float v4 = col_base[(size_t)(l + 4) * EMB_D];
            float v5 = col_base[(size_t)(l + 5) * EMB_D];
            float v6 = col_base[(size_t)(l + 6) * EMB_D];
            float v7 = col_base[(size_t)(l + 7) * EMB_D];
            a0 += sm.s_m[l + 0] * v0;
            a1 += sm.s_m[l + 1] * v1;
            a2 += sm.s_m[l + 2] * v2;
            a3 += sm.s_m[l + 3] * v3;
            a4 += sm.s_m[l + 4] * v4;
            a5 += sm.s_m[l + 5] * v5;
            a6 += sm.s_m[l + 6] * v6;
            a7 += sm.s_m[l + 7] * v7;
        }
        float mean = (((a0 + a1) + (a2 + a3)) + ((a4 + a5) + (a6 + a7))) * sm.s_minv;
        out_mean[(size_t)bs * EMB_D + ocol] = mean;
    }
}

extern "C" void kernel_launch(void* const* d_in, const int* in_sizes, int n_in,
                              void* d_out, int out_size)
{
    const int*   sent = (const int*)  d_in[0];
    const int*   mask = (const int*)  d_in[1];
    const int*   pred = (const int*)  d_in[2];
    const int*   a0   = (const int*)  d_in[3];
    const int*   a1   = (const int*)  d_in[4];
    const float* emb  = (const float*)d_in[5];
    float*       out  = (float*)      d_out;

    const int BS = in_sizes[0] / L_TOK;   // 256

    slmuse_fused_kernel<<<BS * NCHUNK, BDIM>>>(
        sent, mask, pred, a0, a1, emb, out, BS);
}

// round 5
// speedup vs baseline: 1.1017x; 1.1017x over previous
#include <cuda_runtime.h>
#include <cuda_bf16.h>

// Problem constants (fixed by the reference: B=16,S=16 -> BS=256)
#define L_TOK   128          // tokens per sentence
#define NARG    8            // A
#define NTOK    8            // T
#define EMB_D   768          // D
#define DC      256          // D-chunk per CTA
#define NCHUNK  (EMB_D / DC) // 3
#define NP      24           // 3 arg-sets * NARG
#define BDIM    256

// flat entry: l (bits 0..6) | w (bits 7..10) | p (bits 11..15)
struct SmemLayout {
    int            s_ids[L_TOK];
    float          s_m[L_TOK];
    int            s_arg[NP * NTOK];
    unsigned char  wtab[NP * L_TOK];     // 3 KB  per (p,l) match weight
    int            cnt[NP];              // entries per p
    int            cursor[NP];           // placement cursors
    int            offs[NP + 1];         // exclusive scan of cnt
    unsigned short flat[NP * L_TOK];     // 6 KB  events sorted by p
    int            s_tot[NP];            // total matched tokens per p
    float          s_inv[NP];            // 1/tot or 0
    float          s_minv;               // 1/max(sum(mask),1)
};

__global__ void __launch_bounds__(BDIM)
slmuse_fused_kernel(const int*   __restrict__ sent_ids,
                    const int*   __restrict__ att_mask,
                    const int*   __restrict__ pred_ids,
                    const int*   __restrict__ arg0_ids,
                    const int*   __restrict__ arg1_ids,
                    const float* __restrict__ emb,
                    float*       __restrict__ out,
                    int BS)
{
    __shared__ SmemLayout sm;

    const int tid   = threadIdx.x;
    const int bs    = blockIdx.x / NCHUNK;
    const int chunk = blockIdx.x % NCHUNK;

    float* out_mean = out;                               // [BS, D]
    float* out_sets = out + (size_t)BS * EMB_D;          // 3 x [BS, A, D]
    const size_t set_stride = (size_t)BS * NARG * EMB_D;

    // ---- Phase 1: stage ids / mask / arg ids ----
    if (tid < L_TOK) {
        sm.s_ids[tid] = sent_ids[(size_t)bs * L_TOK + tid];
        sm.s_m[tid]   = (float)att_mask[(size_t)bs * L_TOK + tid];
    }
    if (tid < NP * NTOK) {                 // 192 threads
        int p = tid / NTOK, t = tid % NTOK;
        int set = p / NARG, a = p % NARG;
        const int* src = (set == 0) ? pred_ids : (set == 1) ? arg0_ids : arg1_ids;
        sm.s_arg[tid] = src[((size_t)bs * NARG + a) * NTOK + t];
    }
    if (tid < NP) { sm.cnt[tid] = 0; sm.s_tot[tid] = 0; }
    __syncthreads();

    // ---- Phase 2a: match weights + per-p counts (12 iterations) ----
    for (int task = tid; task < NP * L_TOK; task += BDIM) {
        int p = task >> 7;
        int l = task & (L_TOK - 1);
        int sid = sm.s_ids[l];
        int w = 0;
        #pragma unroll
        for (int t = 0; t < NTOK; t++) {
            int aid = sm.s_arg[p * NTOK + t];
            w += (aid != 0 && aid == sid) ? 1 : 0;
        }
        sm.wtab[task] = (unsigned char)w;
        if (w) {
            atomicAdd(&sm.cnt[p], 1);
            atomicAdd(&sm.s_tot[p], w);
        }
    }
    __syncthreads();

    // ---- Phase 2b: exclusive scan of counts (24 elems, 1 thread) ----
    if (tid == 0) {
        int run = 0;
        #pragma unroll
        for (int p = 0; p < NP; p++) { sm.offs[p] = run; run += sm.cnt[p]; }
        sm.offs[NP] = run;

        float ms = 0.f;
        #pragma unroll 8
        for (int l = 0; l < L_TOK; l++) ms += sm.s_m[l];
        sm.s_minv = 1.f / fmaxf(ms, 1.f);
    }
    __syncthreads();
    if (tid < NP) {
        sm.cursor[tid] = sm.offs[tid];
        int tot = sm.s_tot[tid];
        sm.s_inv[tid] = (tot > 0) ? (1.f / (float)tot) : 0.f;
    }
    __syncthreads();

    // ---- Phase 2c: place events into p-sorted flat list ----
    for (int task = tid; task < NP * L_TOK; task += BDIM) {
        int w = sm.wtab[task];
        if (w) {
            int p = task >> 7;
            int l = task & (L_TOK - 1);
            int pos = atomicAdd(&sm.cursor[p], 1);
            sm.flat[pos] = (unsigned short)(l | (w << 7) | (p << 11));
        }
    }
    __syncthreads();

    const float* col_base = emb + (size_t)bs * L_TOK * EMB_D
                                + (size_t)chunk * DC + tid;
    const size_t ocol = (size_t)chunk * DC + tid;

    // ---- Phase M: mean pool FIRST — dense coalesced stream, MLP=8.
    // Warms L2 with every row this CTA will need in the sparse walk.
    {
        float a0 = 0.f, a1 = 0.f, a2 = 0.f, a3 = 0.f;
        float a4 = 0.f, a5 = 0.f, a6 = 0.f, a7 = 0.f;
        #pragma unroll 2
        for (int l = 0; l < L_TOK; l += 8) {
            float v0 = col_base[(size_t)(l + 0) * EMB_D];
            float v1 = col_base[(size_t)(l + 1) * EMB_D];
            float v2 = col_base[(size_t)(l + 2) * EMB_D];
            float v3 = col_base[(size_t)(l + 3) * EMB_D];
            float v4 = col_base[(size_t)(l + 4) * EMB_D];
            float v5 = col_base[(size_t)(l + 5) * EMB_D];
            float v6 = col_base[(size_t)(l + 6) * EMB_D];
            float v7 = col_base[(size_t)(l + 7) * EMB_D];
            a0 += sm.s_m[l + 0] * v0;
            a1 += sm.s_m[l + 1] * v1;
            a2 += sm.s_m[l + 2] * v2;
            a3 += sm.s_m[l + 3] * v3;
            a4 += sm.s_m[l + 4] * v4;
            a5 += sm.s_m[l + 5] * v5;
            a6 += sm.s_m[l + 6] * v6;
            a7 += sm.s_m[l + 7] * v7;
        }
        float mean = (((a0 + a1) + (a2 + a3)) + ((a4 + a5) + (a6 + a7))) * sm.s_minv;
        out_mean[(size_t)bs * EMB_D + ocol] = mean;
    }

    // ---- Phase S: sparse arg sums — p-sorted register walk, MLP=8,
    // loads hit warm L2. Direct emission at p boundaries.
    {
        const int total = sm.offs[NP];
        float acc = 0.f;
        int curp = 0;

        for (int j0 = 0; j0 < total; j0 += 8) {
            float vals[8];
            int   es[8];
            #pragma unroll
            for (int k = 0; k < 8; k++) {
                int j = j0 + k;
                int e = (j < total) ? (int)sm.flat[j] : (NP << 11);  // sentinel w=0
                es[k]   = e;
                vals[k] = (j < total) ? col_base[(size_t)(e & 127) * EMB_D] : 0.f;
            }
            #pragma unroll
            for (int k = 0; k < 8; k++) {
                int p = es[k] >> 11;
                if (p != curp) {                       // block-uniform branch
                    for (int q = curp; q < p && q < NP; q++) {
                        float res = (q == curp) ? acc * sm.s_inv[q] : 0.f;
                        int set = q >> 3, a = q & 7;
                        out_sets[(size_t)set * set_stride
                                 + ((size_t)bs * NARG + a) * EMB_D + ocol] = res;
                    }
                    curp = p;
                    acc  = 0.f;
                }
                acc += (float)((es[k] >> 7) & 15) * vals[k];
            }
        }
        // tail: remaining p's (including all-empty case)
        for (int q = curp; q < NP; q++) {
            float res = (q == curp) ? acc * sm.s_inv[q] : 0.f;
            int set = q >> 3, a = q & 7;
            out_sets[(size_t)set * set_stride
                     + ((size_t)bs * NARG + a) * EMB_D + ocol] = res;
        }
    }
}

extern "C" void kernel_launch(void* const* d_in, const int* in_sizes, int n_in,
                              void* d_out, int out_size)
{
    const int*   sent = (const int*)  d_in[0];
    const int*   mask = (const int*)  d_in[1];
    const int*   pred = (const int*)  d_in[2];
    const int*   a0   = (const int*)  d_in[3];
    const int*   a1   = (const int*)  d_in[4];
    const float* emb  = (const float*)d_in[5];
    float*       out  = (float*)      d_out;

    const int BS = in_sizes[0] / L_TOK;   // 256

    slmuse_fused_kernel<<<BS * NCHUNK, BDIM>>>(
        sent, mask, pred, a0, a1, emb, out, BS);
}

// round 6
// speedup vs baseline: 1.3150x; 1.1936x over previous
#include <cuda_runtime.h>
#include <cuda_bf16.h>

// Problem constants (fixed by the reference: B=16,S=16 -> BS=256)
#define L_TOK   128          // tokens per sentence
#define NARG    8            // A
#define NTOK    8            // T
#define EMB_D   768          // D
#define D4      (EMB_D / 4)  // 192 float4 per row
#define NP      24           // 3 arg-sets * NARG
#define BDIM    192          // one thread per float4 column group

// flat entry: l (bits 0..6) | w (bits 7..10) | p (bits 11..15)
struct SmemLayout {
    int            s_ids[L_TOK];
    float          s_m[L_TOK];
    int            s_arg[NP * NTOK];
    unsigned char  wtab[NP * L_TOK];     // 3 KB  per (p,l) match weight
    int            cnt[NP];              // entries per p
    int            cursor[NP];           // placement cursors
    int            offs[NP + 1];         // exclusive scan of cnt
    unsigned short flat[NP * L_TOK];     // 6 KB  events sorted by p
    int            s_tot[NP];            // total matched tokens per p
    float          s_inv[NP];            // 1/tot or 0
    float          s_minv;               // 1/max(sum(mask),1)
};

__global__ void __launch_bounds__(BDIM)
slmuse_fused_kernel(const int*   __restrict__ sent_ids,
                    const int*   __restrict__ att_mask,
                    const int*   __restrict__ pred_ids,
                    const int*   __restrict__ arg0_ids,
                    const int*   __restrict__ arg1_ids,
                    const float* __restrict__ emb,
                    float*       __restrict__ out,
                    int BS)
{
    __shared__ SmemLayout sm;

    const int tid = threadIdx.x;
    const int bs  = blockIdx.x;               // one CTA per sentence pair

    float* out_mean = out;                               // [BS, D]
    float* out_sets = out + (size_t)BS * EMB_D;          // 3 x [BS, A, D]
    const size_t set_stride = (size_t)BS * NARG * EMB_D;

    // ---- Phase 1: stage ids / mask / arg ids ----
    if (tid < L_TOK) {
        sm.s_ids[tid] = sent_ids[(size_t)bs * L_TOK + tid];
        sm.s_m[tid]   = (float)att_mask[(size_t)bs * L_TOK + tid];
    }
    {   // NP*NTOK = 192 == BDIM: exactly one element per thread
        int p = tid / NTOK, t = tid % NTOK;
        int set = p / NARG, a = p % NARG;
        const int* src = (set == 0) ? pred_ids : (set == 1) ? arg0_ids : arg1_ids;
        sm.s_arg[tid] = src[((size_t)bs * NARG + a) * NTOK + t];
    }
    if (tid < NP) { sm.cnt[tid] = 0; sm.s_tot[tid] = 0; }
    __syncthreads();

    // ---- Phase 2a: match weights + per-p counts (16 iterations) ----
    for (int task = tid; task < NP * L_TOK; task += BDIM) {
        int p = task >> 7;
        int l = task & (L_TOK - 1);
        int sid = sm.s_ids[l];
        int w = 0;
        #pragma unroll
        for (int t = 0; t < NTOK; t++) {
            int aid = sm.s_arg[p * NTOK + t];
            w += (aid != 0 && aid == sid) ? 1 : 0;
        }
        sm.wtab[task] = (unsigned char)w;
        if (w) {
            atomicAdd(&sm.cnt[p], 1);
            atomicAdd(&sm.s_tot[p], w);
        }
    }
    __syncthreads();

    // ---- Phase 2b: exclusive scan of counts (24 elems, 1 thread) ----
    if (tid == 0) {
        int run = 0;
        #pragma unroll
        for (int p = 0; p < NP; p++) { sm.offs[p] = run; run += sm.cnt[p]; }
        sm.offs[NP] = run;

        float ms = 0.f;
        #pragma unroll 8
        for (int l = 0; l < L_TOK; l++) ms += sm.s_m[l];
        sm.s_minv = 1.f / fmaxf(ms, 1.f);
    }
    __syncthreads();
    if (tid < NP) {
        sm.cursor[tid] = sm.offs[tid];
        int tot = sm.s_tot[tid];
        sm.s_inv[tid] = (tot > 0) ? (1.f / (float)tot) : 0.f;
    }
    __syncthreads();

    // ---- Phase 2c: place events into p-sorted flat list ----
    for (int task = tid; task < NP * L_TOK; task += BDIM) {
        int w = sm.wtab[task];
        if (w) {
            int p = task >> 7;
            int l = task & (L_TOK - 1);
            int pos = atomicAdd(&sm.cursor[p], 1);
            sm.flat[pos] = (unsigned short)(l | (w << 7) | (p << 11));
        }
    }
    __syncthreads();

    // Thread tid owns float4 column group tid (columns 4*tid .. 4*tid+3).
    const float4* cb = reinterpret_cast<const float4*>(
                           emb + (size_t)bs * L_TOK * EMB_D) + tid;
    const int ocol = 4 * tid;   // element column in output rows

    // ---- Phase M: mean pool — dense coalesced float4 stream, MLP=8 ----
    {
        float4 a0 = {0,0,0,0}, a1 = {0,0,0,0}, a2 = {0,0,0,0}, a3 = {0,0,0,0};
        float4 a4 = {0,0,0,0}, a5 = {0,0,0,0}, a6 = {0,0,0,0}, a7 = {0,0,0,0};
        #pragma unroll 2
        for (int l = 0; l < L_TOK; l += 8) {
            float4 v0 = cb[(l + 0) * D4];
            float4 v1 = cb[(l + 1) * D4];
            float4 v2 = cb[(l + 2) * D4];
            float4 v3 = cb[(l + 3) * D4];
            float4 v4 = cb[(l + 4) * D4];
            float4 v5 = cb[(l + 5) * D4];
            float4 v6 = cb[(l + 6) * D4];
            float4 v7 = cb[(l + 7) * D4];
            float m0 = sm.s_m[l + 0], m1 = sm.s_m[l + 1];
            float m2 = sm.s_m[l + 2], m3 = sm.s_m[l + 3];
            float m4 = sm.s_m[l + 4], m5 = sm.s_m[l + 5];
            float m6 = sm.s_m[l + 6], m7 = sm.s_m[l + 7];
            a0.x += m0*v0.x; a0.y += m0*v0.y; a0.z += m0*v0.z; a0.w += m0*v0.w;
            a1.x += m1*v1.x; a1.y += m1*v1.y; a1.z += m1*v1.z; a1.w += m1*v1.w;
            a2.x += m2*v2.x; a2.y += m2*v2.y; a2.z += m2*v2.z; a2.w += m2*v2.w;
            a3.x += m3*v3.x; a3.y += m3*v3.y; a3.z += m3*v3.z; a3.w += m3*v3.w;
            a4.x += m4*v4.x; a4.y += m4*v4.y; a4.z += m4*v4.z; a4.w += m4*v4.w;
            a5.x += m5*v5.x; a5.y += m5*v5.y; a5.z += m5*v5.z; a5.w += m5*v5.w;
            a6.x += m6*v6.x; a6.y += m6*v6.y; a6.z += m6*v6.z; a6.w += m6*v6.w;
            a7.x += m7*v7.x; a7.y += m7*v7.y; a7.z += m7*v7.z; a7.w += m7*v7.w;
        }
        float minv = sm.s_minv;
        float4 r;
        r.x = (((a0.x+a1.x)+(a2.x+a3.x))+((a4.x+a5.x)+(a6.x+a7.x))) * minv;
        r.y = (((a0.y+a1.y)+(a2.y+a3.y))+((a4.y+a5.y)+(a6.y+a7.y))) * minv;
        r.z = (((a0.z+a1.z)+(a2.z+a3.z))+((a4.z+a5.z)+(a6.z+a7.z))) * minv;
        r.w = (((a0.w+a1.w)+(a2.w+a3.w))+((a4.w+a5.w)+(a6.w+a7.w))) * minv;
        *reinterpret_cast<float4*>(out_mean + (size_t)bs * EMB_D + ocol) = r;
    }

    // ---- Phase S: sparse arg sums — p-sorted register walk, float4,
    // MLP=8, rows hit warm L2. Emission at block-uniform p boundaries.
    {
        const int total = sm.offs[NP];
        float4 acc = {0,0,0,0};
        int curp = 0;

        for (int j0 = 0; j0 < total; j0 += 8) {
            float4 vals[8];
            int    es[8];
            #pragma unroll
            for (int k = 0; k < 8; k++) {
                int j = j0 + k;
                int e = (j < total) ? (int)sm.flat[j] : (NP << 11);  // sentinel
                es[k] = e;
                if (j < total) vals[k] = cb[(e & 127) * D4];
                else           vals[k] = make_float4(0.f, 0.f, 0.f, 0.f);
            }
            #pragma unroll
            for (int k = 0; k < 8; k++) {
                int p = es[k] >> 11;
                if (p != curp) {                       // block-uniform branch
                    for (int q = curp; q < p && q < NP; q++) {
                        float s = (q == curp) ? sm.s_inv[q] : 0.f;
                        float4 r;
                        r.x = acc.x * s; r.y = acc.y * s;
                        r.z = acc.z * s; r.w = acc.w * s;
                        int set = q >> 3, a = q & 7;
                        *reinterpret_cast<float4*>(
                            out_sets + (size_t)set * set_stride
                            + ((size_t)bs * NARG + a) * EMB_D + ocol) = r;
                    }
                    curp = p;
                    acc = make_float4(0.f, 0.f, 0.f, 0.f);
                }
                float w = (float)((es[k] >> 7) & 15);
                acc.x += w * vals[k].x; acc.y += w * vals[k].y;
                acc.z += w * vals[k].z; acc.w += w * vals[k].w;
            }
        }
        // tail: remaining p's (including all-empty case)
        for (int q = curp; q < NP; q++) {
            float s = (q == curp) ? sm.s_inv[q] : 0.f;
            float4 r;
            r.x = acc.x * s; r.y = acc.y * s; r.z = acc.z * s; r.w = acc.w * s;
            int set = q >> 3, a = q & 7;
            *reinterpret_cast<float4*>(
                out_sets + (size_t)set * set_stride
                + ((size_t)bs * NARG + a) * EMB_D + ocol) = r;
        }
    }
}

extern "C" void kernel_launch(void* const* d_in, const int* in_sizes, int n_in,
                              void* d_out, int out_size)
{
    const int*   sent = (const int*)  d_in[0];
    const int*   mask = (const int*)  d_in[1];
    const int*   pred = (const int*)  d_in[2];
    const int*   a0   = (const int*)  d_in[3];
    const int*   a1   = (const int*)  d_in[4];
    const float* emb  = (const float*)d_in[5];
    float*       out  = (float*)      d_out;

    const int BS = in_sizes[0] / L_TOK;   // 256

    slmuse_fused_kernel<<<BS, BDIM>>>(
        sent, mask, pred, a0, a1, emb, out, BS);
}

// round 7
// speedup vs baseline: 1.8767x; 1.4272x over previous
#include <cuda_runtime.h>
#include <cuda_bf16.h>

// Problem constants (fixed by the reference: B=16,S=16 -> BS=256)
#define L_TOK   128          // tokens per sentence
#define NARG    8            // A
#define NTOK    8            // T
#define EMB_D   768          // D
#define D4      (EMB_D / 4)  // 192 float4 per row
#define NP      24           // 3 arg-sets * NARG
#define BDIM    384          // 192 mean threads + 192 sparse threads

// flat entry: l (bits 0..6) | w (bits 7..10) | p (bits 11..15)
struct SmemLayout {
    int            s_ids[L_TOK];
    float          s_m[L_TOK];
    int            s_arg[NP * NTOK];
    unsigned char  wtab[NP * L_TOK];     // 3 KB  per (p,l) match weight
    int            cnt[NP];              // entries per p
    int            cursor[NP];           // placement cursors
    int            offs[NP + 1];         // exclusive scan of cnt
    unsigned short flat[NP * L_TOK];     // 6 KB  events sorted by p
    int            s_tot[NP];            // total matched tokens per p
    float          s_inv[NP];            // 1/tot or 0
    float          s_minv;               // 1/max(sum(mask),1)
};

__global__ void __launch_bounds__(BDIM)
slmuse_fused_kernel(const int*   __restrict__ sent_ids,
                    const int*   __restrict__ att_mask,
                    const int*   __restrict__ pred_ids,
                    const int*   __restrict__ arg0_ids,
                    const int*   __restrict__ arg1_ids,
                    const float* __restrict__ emb,
                    float*       __restrict__ out,
                    int BS)
{
    __shared__ SmemLayout sm;

    const int tid  = threadIdx.x;
    const int bs   = blockIdx.x;              // one CTA per sentence pair
    const int half = tid / D4;                // 0 = mean warps, 1 = sparse warps
    const int ctid = tid - half * D4;         // float4 column group 0..191

    float* out_mean = out;                               // [BS, D]
    float* out_sets = out + (size_t)BS * EMB_D;          // 3 x [BS, A, D]
    const size_t set_stride = (size_t)BS * NARG * EMB_D;

    // ---- Phase 1: stage ids / mask / arg ids (all 384 threads) ----
    if (tid < L_TOK) {
        sm.s_ids[tid] = sent_ids[(size_t)bs * L_TOK + tid];
        sm.s_m[tid]   = (float)att_mask[(size_t)bs * L_TOK + tid];
    }
    if (tid < NP * NTOK) {                 // 192 elements
        int p = tid / NTOK, t = tid % NTOK;
        int set = p / NARG, a = p % NARG;
        const int* src = (set == 0) ? pred_ids : (set == 1) ? arg0_ids : arg1_ids;
        sm.s_arg[tid] = src[((size_t)bs * NARG + a) * NTOK + t];
    }
    if (tid < NP) { sm.cnt[tid] = 0; sm.s_tot[tid] = 0; }
    __syncthreads();

    // ---- Phase 2a: match weights + per-p counts (8 iterations) ----
    for (int task = tid; task < NP * L_TOK; task += BDIM) {
        int p = task >> 7;
        int l = task & (L_TOK - 1);
        int sid = sm.s_ids[l];
        int w = 0;
        #pragma unroll
        for (int t = 0; t < NTOK; t++) {
            int aid = sm.s_arg[p * NTOK + t];
            w += (aid != 0 && aid == sid) ? 1 : 0;
        }
        sm.wtab[task] = (unsigned char)w;
        if (w) {
            atomicAdd(&sm.cnt[p], 1);
            atomicAdd(&sm.s_tot[p], w);
        }
    }
    __syncthreads();

    // ---- Phase 2b: exclusive scan of counts (24 elems, 1 thread) ----
    if (tid == 0) {
        int run = 0;
        #pragma unroll
        for (int p = 0; p < NP; p++) { sm.offs[p] = run; run += sm.cnt[p]; }
        sm.offs[NP] = run;

        float ms = 0.f;
        #pragma unroll 8
        for (int l = 0; l < L_TOK; l++) ms += sm.s_m[l];
        sm.s_minv = 1.f / fmaxf(ms, 1.f);
    }
    __syncthreads();
    if (tid < NP) {
        sm.cursor[tid] = sm.offs[tid];
        int tot = sm.s_tot[tid];
        sm.s_inv[tid] = (tot > 0) ? (1.f / (float)tot) : 0.f;
    }
    __syncthreads();

    // ---- Phase 2c: place events into p-sorted flat list ----
    for (int task = tid; task < NP * L_TOK; task += BDIM) {
        int w = sm.wtab[task];
        if (w) {
            int p = task >> 7;
            int l = task & (L_TOK - 1);
            int pos = atomicAdd(&sm.cursor[p], 1);
            sm.flat[pos] = (unsigned short)(l | (w << 7) | (p << 11));
        }
    }
    __syncthreads();

    // Column base for this thread's 4 columns.
    const float4* cb = reinterpret_cast<const float4*>(
                           emb + (size_t)bs * L_TOK * EMB_D) + ctid;
    const int ocol = 4 * ctid;

    if (half == 0) {
        // ======== MEAN WARPS: dense coalesced float4 stream, MLP=8 ========
        float4 a0 = {0,0,0,0}, a1 = {0,0,0,0}, a2 = {0,0,0,0}, a3 = {0,0,0,0};
        float4 a4 = {0,0,0,0}, a5 = {0,0,0,0}, a6 = {0,0,0,0}, a7 = {0,0,0,0};
        #pragma unroll 2
        for (int l = 0; l < L_TOK; l += 8) {
            float4 v0 = cb[(l + 0) * D4];
            float4 v1 = cb[(l + 1) * D4];
            float4 v2 = cb[(l + 2) * D4];
            float4 v3 = cb[(l + 3) * D4];
            float4 v4 = cb[(l + 4) * D4];
            float4 v5 = cb[(l + 5) * D4];
            float4 v6 = cb[(l + 6) * D4];
            float4 v7 = cb[(l + 7) * D4];
            float m0 = sm.s_m[l + 0], m1 = sm.s_m[l + 1];
            float m2 = sm.s_m[l + 2], m3 = sm.s_m[l + 3];
            float m4 = sm.s_m[l + 4], m5 = sm.s_m[l + 5];
            float m6 = sm.s_m[l + 6], m7 = sm.s_m[l + 7];
            a0.x += m0*v0.x; a0.y += m0*v0.y; a0.z += m0*v0.z; a0.w += m0*v0.w;
            a1.x += m1*v1.x; a1.y += m1*v1.y; a1.z += m1*v1.z; a1.w += m1*v1.w;
            a2.x += m2*v2.x; a2.y += m2*v2.y; a2.z += m2*v2.z; a2.w += m2*v2.w;
            a3.x += m3*v3.x; a3.y += m3*v3.y; a3.z += m3*v3.z; a3.w += m3*v3.w;
            a4.x += m4*v4.x; a4.y += m4*v4.y; a4.z += m4*v4.z; a4.w += m4*v4.w;
            a5.x += m5*v5.x; a5.y += m5*v5.y; a5.z += m5*v5.z; a5.w += m5*v5.w;
            a6.x += m6*v6.x; a6.y += m6*v6.y; a6.z += m6*v6.z; a6.w += m6*v6.w;
            a7.x += m7*v7.x; a7.y += m7*v7.y; a7.z += m7*v7.z; a7.w += m7*v7.w;
        }
        float minv = sm.s_minv;
        float4 r;
        r.x = (((a0.x+a1.x)+(a2.x+a3.x))+((a4.x+a5.x)+(a6.x+a7.x))) * minv;
        r.y = (((a0.y+a1.y)+(a2.y+a3.y))+((a4.y+a5.y)+(a6.y+a7.y))) * minv;
        r.z = (((a0.z+a1.z)+(a2.z+a3.z))+((a4.z+a5.z)+(a6.z+a7.z))) * minv;
        r.w = (((a0.w+a1.w)+(a2.w+a3.w))+((a4.w+a5.w)+(a6.w+a7.w))) * minv;
        *reinterpret_cast<float4*>(out_mean + (size_t)bs * EMB_D + ocol) = r;
    } else {
        // ======== SPARSE WARPS: p-sorted register walk, float4, MLP=8 ======
        const int total = sm.offs[NP];
        float4 acc = {0,0,0,0};
        int curp = 0;

        for (int j0 = 0; j0 < total; j0 += 8) {
            float4 vals[8];
            int    es[8];
            #pragma unroll
            for (int k = 0; k < 8; k++) {
                int j = j0 + k;
                int e = (j < total) ? (int)sm.flat[j] : (NP << 11);  // sentinel
                es[k] = e;
                if (j < total) vals[k] = cb[(e & 127) * D4];
                else           vals[k] = make_float4(0.f, 0.f, 0.f, 0.f);
            }
            #pragma unroll
            for (int k = 0; k < 8; k++) {
                int p = es[k] >> 11;
                if (p != curp) {                       // uniform across half
                    for (int q = curp; q < p && q < NP; q++) {
                        float s = (q == curp) ? sm.s_inv[q] : 0.f;
                        float4 r;
                        r.x = acc.x * s; r.y = acc.y * s;
                        r.z = acc.z * s; r.w = acc.w * s;
                        int set = q >> 3, a = q & 7;
                        *reinterpret_cast<float4*>(
                            out_sets + (size_t)set * set_stride
                            + ((size_t)bs * NARG + a) * EMB_D + ocol) = r;
                    }
                    curp = p;
                    acc = make_float4(0.f, 0.f, 0.f, 0.f);
                }
                float w = (float)((es[k] >> 7) & 15);
                acc.x += w * vals[k].x; acc.y += w * vals[k].y;
                acc.z += w * vals[k].z; acc.w += w * vals[k].w;
            }
        }
        // tail: remaining p's (including all-empty case)
        for (int q = curp; q < NP; q++) {
            float s = (q == curp) ? sm.s_inv[q] : 0.f;
            float4 r;
            r.x = acc.x * s; r.y = acc.y * s; r.z = acc.z * s; r.w = acc.w * s;
            int set = q >> 3, a = q & 7;
            *reinterpret_cast<float4*>(
                out_sets + (size_t)set * set_stride
                + ((size_t)bs * NARG + a) * EMB_D + ocol) = r;
        }
    }
}

extern "C" void kernel_launch(void* const* d_in, const int* in_sizes, int n_in,
                              void* d_out, int out_size)
{
    const int*   sent = (const int*)  d_in[0];
    const int*   mask = (const int*)  d_in[1];
    const int*   pred = (const int*)  d_in[2];
    const int*   a0   = (const int*)  d_in[3];
    const int*   a1   = (const int*)  d_in[4];
    const float* emb  = (const float*)d_in[5];
    float*       out  = (float*)      d_out;

    const int BS = in_sizes[0] / L_TOK;   // 256

    slmuse_fused_kernel<<<BS, BDIM>>>(
        sent, mask, pred, a0, a1, emb, out, BS);
}